// round 15
// baseline (speedup 1.0000x reference)
#include <cuda_runtime.h>
#include <cuda_bf16.h>
#include <math.h>
#include <cstdint>

#define NB   4096
#define ND   512
#define NPOS 8192
#define INV_T 14.2857142857142857f
#define EXP2_SCALE 20.609929155566063f   /* INV_T * log2(e) */
#define NCOLT 32
#define NTILE (NCOLT * (NCOLT + 1) / 2)  /* 528 aa tiles */
#define POSB  (NB / 8)                   /* 512 posdot blocks */
#define NLOSSB (NB / 8)                  /* 512 loss blocks */
#define POS_BASE  NTILE                  /* 528 */
#define LOSS_BASE (NTILE + POSB)         /* 1040 */
#define TOTAL_BLKS (LOSS_BASE + NLOSSB)  /* 1552 */
#define NPROD (NTILE + POSB)             /* 1040 producers */

// ---- scratch (zero-init first launch; reset by last loss block each launch) ----
__device__ __nv_bfloat16 g_abf16[NB * ND];
__device__ float         g_partial[NB * NCOLT];
__device__ float         g_logits[NPOS];
__device__ float         g_losspart[NLOSSB];
__device__ int           g_done;    // producer completion counter
__device__ int           g_count;   // loss-block completion counter

__device__ __forceinline__ uint32_t smem_u32(const void* p) {
    uint32_t a;
    asm("{ .reg .u64 t; cvta.to.shared.u64 t, %1; cvt.u32.u64 %0, t; }" : "=r"(a) : "l"(p));
    return a;
}
__device__ __forceinline__ float ex2(float x) {
    float r;
    asm("ex2.approx.ftz.f32 %0, %1;" : "=f"(r) : "f"(x));
    return r;
}
__device__ __forceinline__ int ld_acq(const int* p) {
    int v;
    asm volatile("ld.acquire.gpu.s32 %0, [%1];" : "=r"(v) : "l"(p));
    return v;
}

// ---------------------------------------------------------------------------
// 1) L2-normalize anchors -> bf16. One row per warp (R12-proven config).
// ---------------------------------------------------------------------------
__global__ __launch_bounds__(128) void normalize_kernel(const float* __restrict__ a) {
    int warp = threadIdx.x >> 5;
    int lane = threadIdx.x & 31;
    int row  = blockIdx.x * 4 + warp;

    const float4* src = (const float4*)(a + (size_t)row * ND);
    uint2* bdst = (uint2*)(g_abf16 + (size_t)row * ND);

    float4 v[4];
    float ss = 0.f;
#pragma unroll
    for (int q = 0; q < 4; q++) v[q] = src[lane + 32 * q];
#pragma unroll
    for (int q = 0; q < 4; q++)
        ss += v[q].x * v[q].x + v[q].y * v[q].y + v[q].z * v[q].z + v[q].w * v[q].w;
#pragma unroll
    for (int o = 16; o > 0; o >>= 1) ss += __shfl_xor_sync(0xffffffffu, ss, o);

    float inv = rsqrtf(ss);
#pragma unroll
    for (int q = 0; q < 4; q++) {
        float4 w = v[q];
        __nv_bfloat162 lo = __floats2bfloat162_rn(w.x * inv, w.y * inv);
        __nv_bfloat162 hi = __floats2bfloat162_rn(w.z * inv, w.w * inv);
        uint2 pk; pk.x = *(uint32_t*)&lo; pk.y = *(uint32_t*)&hi;
        bdst[lane + 32 * q] = pk;
    }
}

// ---------------------------------------------------------------------------
// 2) Mega-kernel: aa tiles (0..527) -> posdot (528..1039) -> loss (1040..1551).
//    Producers bump g_done; loss blocks (dispatched last) wait for 1040,
//    then finish the loss and the deterministic mean.
// ---------------------------------------------------------------------------
#define KC 32
#define NCHUNK (ND / KC)      // 16
#define TILE_BYTES (128 * 64) // 8KB
#define SMEM_AA (6 * TILE_BYTES)   // 48KB dynamic

__global__ __launch_bounds__(256, 2) void mega_kernel(const float* __restrict__ anchor,
                                                      const float* __restrict__ pos,
                                                      float* __restrict__ out) {
    extern __shared__ __align__(128) char dyn[];
    const int bid = blockIdx.x;
    const int tid = threadIdx.x;
    const int wid = tid >> 5;
    const int l   = tid & 31;

    // ================= posdot blocks (raw fp32, no deps) =================
    if (bid >= POS_BASE && bid < LOSS_BASE) {
        const int b = (bid - POS_BASE) * 8 + wid;
        const float4* av  = (const float4*)(anchor + (size_t)b * ND);
        const float4* pv0 = (const float4*)(pos + (size_t)(2 * b) * ND);
        const float4* pv1 = (const float4*)(pos + (size_t)(2 * b + 1) * ND);

        float4 a4[4], p0[4], p1[4];
#pragma unroll
        for (int q = 0; q < 4; q++) a4[q] = av[l + 32 * q];
#pragma unroll
        for (int q = 0; q < 4; q++) p0[q] = pv0[l + 32 * q];
#pragma unroll
        for (int q = 0; q < 4; q++) p1[q] = pv1[l + 32 * q];

        float daa = 0.f, d0 = 0.f, n0 = 0.f, d1 = 0.f, n1 = 0.f;
#pragma unroll
        for (int q = 0; q < 4; q++) {
            daa += a4[q].x * a4[q].x + a4[q].y * a4[q].y + a4[q].z * a4[q].z + a4[q].w * a4[q].w;
            d0  += a4[q].x * p0[q].x + a4[q].y * p0[q].y + a4[q].z * p0[q].z + a4[q].w * p0[q].w;
            n0  += p0[q].x * p0[q].x + p0[q].y * p0[q].y + p0[q].z * p0[q].z + p0[q].w * p0[q].w;
            d1  += a4[q].x * p1[q].x + a4[q].y * p1[q].y + a4[q].z * p1[q].z + a4[q].w * p1[q].w;
            n1  += p1[q].x * p1[q].x + p1[q].y * p1[q].y + p1[q].z * p1[q].z + p1[q].w * p1[q].w;
        }
#pragma unroll
        for (int o = 16; o > 0; o >>= 1) {
            daa += __shfl_xor_sync(0xffffffffu, daa, o);
            d0  += __shfl_xor_sync(0xffffffffu, d0, o);
            n0  += __shfl_xor_sync(0xffffffffu, n0, o);
            d1  += __shfl_xor_sync(0xffffffffu, d1, o);
            n1  += __shfl_xor_sync(0xffffffffu, n1, o);
        }
        if (l == 0) {
            float ia = rsqrtf(daa);
            g_logits[2 * b]     = d0 * rsqrtf(n0) * ia * INV_T;
            g_logits[2 * b + 1] = d1 * rsqrtf(n1) * ia * INV_T;
        }
        __threadfence();
        __syncthreads();
        if (tid == 0) atomicAdd(&g_done, 1);
        return;
    }

    // ================= loss blocks (dispatched last; wait on producers) ======
    if (bid >= LOSS_BASE) {
        __shared__ float sh[8];
        __shared__ int slast;
        const int bid2 = bid - LOSS_BASE;
        const int b    = bid2 * 8 + wid;

        if (tid == 0) {
            while (ld_acq(&g_done) < NPROD) __nanosleep(128);
        }
        __syncthreads();   // all producer output visible

        float np = g_partial[(size_t)b * NCOLT + l];
#pragma unroll
        for (int o = 16; o > 0; o >>= 1) np += __shfl_xor_sync(0xffffffffu, np, o);

        if (l == 0) {
            float ps0 = g_logits[2 * b];
            float ps1 = g_logits[2 * b + 1];
            float l0  = logf(expf(ps0) + np + 1e-8f) - ps0;
            float l1  = logf(expf(ps1) + np + 1e-8f) - ps1;
            sh[wid] = l0 + l1;
        }
        __syncthreads();

        if (tid == 0) {
            float s = 0.f;
#pragma unroll
            for (int w = 0; w < 8; w++) s += sh[w];
            g_losspart[bid2] = s;
            __threadfence();
            int old = atomicAdd(&g_count, 1);
            slast = (old == NLOSSB - 1) ? 1 : 0;
        }
        __syncthreads();

        if (slast) {
            __shared__ float fr[256];
            float s = g_losspart[tid] + g_losspart[tid + 256];
            fr[tid] = s;
            __syncthreads();
            for (int o = 128; o > 0; o >>= 1) {
                if (tid < o) fr[tid] += fr[tid + o];
                __syncthreads();
            }
            if (tid == 0) {
                out[0] = fr[0] * (1.0f / (float)NPOS);
                g_done = 0;     // reset cross-launch state (graph replay)
                g_count = 0;
            }
        }
        return;
    }

    // ================= aa tiles (R12-proven mainloop) =================
    __shared__ float rs_row[128][4];
    __shared__ float rs_col[128][2];

    const int idx = bid;
    int bx = (int)((sqrtf(8.0f * idx + 1.0f) - 1.0f) * 0.5f);
    while ((bx + 1) * (bx + 2) / 2 <= idx) ++bx;
    while (bx * (bx + 1) / 2 > idx) --bx;
    const int by = idx - bx * (bx + 1) / 2;
    const bool diag = (bx == by);

    const int wr  = wid & 1;
    const int wc  = wid >> 1;
    const int row0 = by * 128;
    const int col0 = bx * 128;

    const uint32_t sa_base = smem_u32(dyn);
    const uint32_t sb_base = sa_base + 3 * TILE_BYTES;
    const char* gsrc = (const char*)g_abf16;

    const int ra = (l & 7) | (((l >> 3) & 1) << 3);
    const int sa_hi = l >> 4;
    const int rb = (l & 7) | ((l >> 4) << 3);
    const int sb_hi = (l >> 3) & 1;

    uint32_t offA[2], offB[2];
#pragma unroll
    for (int kc = 0; kc < 2; kc++) {
        offA[kc] = ra * 64 + (((2 * kc + sa_hi) ^ ((ra >> 1) & 3)) << 4);
        offB[kc] = rb * 64 + (((2 * kc + sb_hi) ^ ((rb >> 1) & 3)) << 4);
    }

    int ld_row[2], ld_slot[2];
    uint32_t ld_dst[2];
#pragma unroll
    for (int t = 0; t < 2; t++) {
        int i2 = tid + t * 256;
        ld_row[t]  = i2 >> 2;
        ld_slot[t] = i2 & 3;
        int sw = ld_slot[t] ^ ((ld_row[t] >> 1) & 3);
        ld_dst[t] = ld_row[t] * 64 + sw * 16;
    }

    float acc[4][4][4];
#pragma unroll
    for (int i = 0; i < 4; i++)
#pragma unroll
        for (int j = 0; j < 4; j++)
#pragma unroll
            for (int q = 0; q < 4; q++) acc[i][j][q] = 0.f;

#define ISSUE_CHUNK(c, nb) do {                                               \
    int kbyte = (c) * KC * 2;                                                 \
    _Pragma("unroll")                                                         \
    for (int t = 0; t < 2; t++) {                                             \
        const char* srcA = gsrc + ((size_t)(row0 + ld_row[t]) * ND) * 2 + kbyte + ld_slot[t] * 16; \
        const char* srcB = gsrc + ((size_t)(col0 + ld_row[t]) * ND) * 2 + kbyte + ld_slot[t] * 16; \
        asm volatile("cp.async.cg.shared.global [%0], [%1], 16;"              \
            :: "r"(sa_base + (nb) * TILE_BYTES + ld_dst[t]), "l"(srcA) : "memory"); \
        asm volatile("cp.async.cg.shared.global [%0], [%1], 16;"              \
            :: "r"(sb_base + (nb) * TILE_BYTES + ld_dst[t]), "l"(srcB) : "memory"); \
    }                                                                         \
    asm volatile("cp.async.commit_group;" ::: "memory");                      \
} while (0)

    ISSUE_CHUNK(0, 0);
    ISSUE_CHUNK(1, 1);

    for (int c = 0; c < NCHUNK; c++) {
        if (c < NCHUNK - 1) asm volatile("cp.async.wait_group 1;" ::: "memory");
        else                asm volatile("cp.async.wait_group 0;" ::: "memory");
        __syncthreads();

        int p = c + 2;
        if (p < NCHUNK) ISSUE_CHUNK(p, p % 3);

        const int buf = c % 3;
        const uint32_t aw = sa_base + buf * TILE_BYTES + wr * 64 * 64;
        const uint32_t bw = sb_base + buf * TILE_BYTES + wc * 32 * 64;

#pragma unroll
        for (int kc = 0; kc < 2; kc++) {
            uint32_t af[4][4];
#pragma unroll
            for (int mf = 0; mf < 4; mf++) {
                asm volatile("ldmatrix.sync.aligned.m8n8.x4.shared.b16 {%0,%1,%2,%3}, [%4];"
                    : "=r"(af[mf][0]), "=r"(af[mf][1]), "=r"(af[mf][2]), "=r"(af[mf][3])
                    : "r"(aw + mf * 16 * 64 + offA[kc]));
            }
            uint32_t bf[4][2];
#pragma unroll
            for (int p2 = 0; p2 < 2; p2++) {
                uint32_t r0, r1, r2, r3;
                asm volatile("ldmatrix.sync.aligned.m8n8.x4.shared.b16 {%0,%1,%2,%3}, [%4];"
                    : "=r"(r0), "=r"(r1), "=r"(r2), "=r"(r3)
                    : "r"(bw + p2 * 16 * 64 + offB[kc]));
                bf[2 * p2][0] = r0; bf[2 * p2][1] = r1;
                bf[2 * p2 + 1][0] = r2; bf[2 * p2 + 1][1] = r3;
            }
#pragma unroll
            for (int mf = 0; mf < 4; mf++)
#pragma unroll
                for (int nf = 0; nf < 4; nf++) {
                    asm volatile(
                        "mma.sync.aligned.m16n8k16.row.col.f32.bf16.bf16.f32 "
                        "{%0,%1,%2,%3}, {%4,%5,%6,%7}, {%8,%9}, {%0,%1,%2,%3};"
                        : "+f"(acc[mf][nf][0]), "+f"(acc[mf][nf][1]),
                          "+f"(acc[mf][nf][2]), "+f"(acc[mf][nf][3])
                        : "r"(af[mf][0]), "r"(af[mf][1]), "r"(af[mf][2]), "r"(af[mf][3]),
                          "r"(bf[nf][0]), "r"(bf[nf][1]));
                }
        }
    }
    __syncthreads();

    const int qrow = l >> 2;
    const int qcol = 2 * (l & 3);

    float cs0[4], cs1[4];
#pragma unroll
    for (int nf = 0; nf < 4; nf++) { cs0[nf] = 0.f; cs1[nf] = 0.f; }

#pragma unroll
    for (int mf = 0; mf < 4; mf++) {
        float slo = 0.f, shi = 0.f;
        int rlo = wr * 64 + mf * 16 + qrow;
#pragma unroll
        for (int nf = 0; nf < 4; nf++) {
            int cb = wc * 32 + nf * 8 + qcol;
            float e0 = ex2(acc[mf][nf][0] * EXP2_SCALE);
            float e1 = ex2(acc[mf][nf][1] * EXP2_SCALE);
            float e2 = ex2(acc[mf][nf][2] * EXP2_SCALE);
            float e3 = ex2(acc[mf][nf][3] * EXP2_SCALE);
            if (diag) {
                if (rlo == cb)         e0 = 0.f;
                if (rlo == cb + 1)     e1 = 0.f;
                if (rlo + 8 == cb)     e2 = 0.f;
                if (rlo + 8 == cb + 1) e3 = 0.f;
            }
            slo += e0 + e1;
            shi += e2 + e3;
            cs0[nf] += e0 + e2;
            cs1[nf] += e1 + e3;
        }
        slo += __shfl_xor_sync(0xffffffffu, slo, 1);
        slo += __shfl_xor_sync(0xffffffffu, slo, 2);
        shi += __shfl_xor_sync(0xffffffffu, shi, 1);
        shi += __shfl_xor_sync(0xffffffffu, shi, 2);
        if ((l & 3) == 0) {
            rs_row[rlo][wc]     = slo;
            rs_row[rlo + 8][wc] = shi;
        }
    }

    if (!diag) {
#pragma unroll
        for (int nf = 0; nf < 4; nf++) {
#pragma unroll
            for (int o = 4; o <= 16; o <<= 1) {
                cs0[nf] += __shfl_xor_sync(0xffffffffu, cs0[nf], o);
                cs1[nf] += __shfl_xor_sync(0xffffffffu, cs1[nf], o);
            }
            if (l < 4) {
                int cb = wc * 32 + nf * 8 + qcol;
                rs_col[cb][wr]     = cs0[nf];
                rs_col[cb + 1][wr] = cs1[nf];
            }
        }
    }
    __syncthreads();

    if (tid < 128) {
        float s = rs_row[tid][0] + rs_row[tid][1] + rs_row[tid][2] + rs_row[tid][3];
        g_partial[(size_t)(row0 + tid) * NCOLT + bx] = s;
        if (!diag) {
            float csum = rs_col[tid][0] + rs_col[tid][1];
            g_partial[(size_t)(col0 + tid) * NCOLT + by] = csum;
        }
    }
    __threadfence();
    __syncthreads();
    if (tid == 0) atomicAdd(&g_done, 1);
}

// ---------------------------------------------------------------------------
extern "C" void kernel_launch(void* const* d_in, const int* in_sizes, int n_in,
                              void* d_out, int out_size) {
    const float* anchor = (const float*)d_in[0];
    const float* pos    = (const float*)d_in[1];
    if (n_in >= 2 && in_sizes[0] > in_sizes[1]) {
        const float* t = anchor; anchor = pos; pos = t;
    }

    cudaFuncSetAttribute(mega_kernel, cudaFuncAttributeMaxDynamicSharedMemorySize,
                         SMEM_AA);

    normalize_kernel<<<NB / 4, 128>>>(anchor);
    mega_kernel<<<TOTAL_BLKS, 256, SMEM_AA>>>(anchor, pos, (float*)d_out);
}

// round 16
// speedup vs baseline: 1.1084x; 1.1084x over previous
#include <cuda_runtime.h>
#include <cuda_bf16.h>
#include <math.h>
#include <cstdint>

#define NB   4096
#define ND   512
#define NPOS 8192
#define INV_T 14.2857142857142857f
#define EXP2_SCALE 20.609929155566063f   /* INV_T * log2(e) */
#define NCOLT 32
#define NTILE (NCOLT * (NCOLT + 1) / 2)  /* 528 aa tiles */
#define POSB  (NB / 8)                   /* 512 posdot blocks */
#define NLOSSB (NB / 8)                  /* 512 loss blocks */

// ---- scratch (no allocation allowed) ----
__device__ __nv_bfloat16 g_abf16[NB * ND];
__device__ float         g_partial[NB * NCOLT];
__device__ float         g_logits[NPOS];
__device__ float         g_losspart[NLOSSB];
__device__ int           g_count;

__device__ __forceinline__ uint32_t smem_u32(const void* p) {
    uint32_t a;
    asm("{ .reg .u64 t; cvta.to.shared.u64 t, %1; cvt.u32.u64 %0, t; }" : "=r"(a) : "l"(p));
    return a;
}
__device__ __forceinline__ float ex2(float x) {
    float r;
    asm("ex2.approx.ftz.f32 %0, %1;" : "=f"(r) : "f"(x));
    return r;
}
__device__ __forceinline__ void grid_dep_sync() {
    asm volatile("griddepcontrol.wait;" ::: "memory");
}

// ---------------------------------------------------------------------------
// 1) L2-normalize anchors -> bf16. One row per warp (R12-proven). Resets count.
// ---------------------------------------------------------------------------
__global__ __launch_bounds__(128) void normalize_kernel(const float* __restrict__ a) {
    if (blockIdx.x == 0 && threadIdx.x == 0) g_count = 0;

    int warp = threadIdx.x >> 5;
    int lane = threadIdx.x & 31;
    int row  = blockIdx.x * 4 + warp;

    const float4* src = (const float4*)(a + (size_t)row * ND);
    uint2* bdst = (uint2*)(g_abf16 + (size_t)row * ND);

    float4 v[4];
    float ss = 0.f;
#pragma unroll
    for (int q = 0; q < 4; q++) v[q] = src[lane + 32 * q];
#pragma unroll
    for (int q = 0; q < 4; q++)
        ss += v[q].x * v[q].x + v[q].y * v[q].y + v[q].z * v[q].z + v[q].w * v[q].w;
#pragma unroll
    for (int o = 16; o > 0; o >>= 1) ss += __shfl_xor_sync(0xffffffffu, ss, o);

    float inv = rsqrtf(ss);
#pragma unroll
    for (int q = 0; q < 4; q++) {
        float4 w = v[q];
        __nv_bfloat162 lo = __floats2bfloat162_rn(w.x * inv, w.y * inv);
        __nv_bfloat162 hi = __floats2bfloat162_rn(w.z * inv, w.w * inv);
        uint2 pk; pk.x = *(uint32_t*)&lo; pk.y = *(uint32_t*)&hi;
        bdst[lane + 32 * q] = pk;
    }
}

// ---------------------------------------------------------------------------
// 2) aa GEMM tiles (0..527) + trailing posdot blocks (528..1039).
//    aa tiles grid-dep-sync on normalize; posdot blocks don't need to.
// ---------------------------------------------------------------------------
#define KC 32
#define NCHUNK (ND / KC)      // 16
#define TILE_BYTES (128 * 64) // 8KB
#define SMEM_AA (6 * TILE_BYTES)   // 48KB dynamic

__global__ __launch_bounds__(256, 2) void aa_mma_kernel(const float* __restrict__ anchor,
                                                        const float* __restrict__ pos) {
    extern __shared__ __align__(128) char dyn[];
    const int tid = threadIdx.x;
    const int wid = tid >> 5;
    const int l   = tid & 31;

    // ============ trailing posdot blocks (raw fp32, no deps — no sync) ======
    if (blockIdx.x >= NTILE) {
        const int b = (blockIdx.x - NTILE) * 8 + wid;
        const float4* av  = (const float4*)(anchor + (size_t)b * ND);
        const float4* pv0 = (const float4*)(pos + (size_t)(2 * b) * ND);
        const float4* pv1 = (const float4*)(pos + (size_t)(2 * b + 1) * ND);

        float4 a4[4], p0[4], p1[4];
#pragma unroll
        for (int q = 0; q < 4; q++) a4[q] = av[l + 32 * q];
#pragma unroll
        for (int q = 0; q < 4; q++) p0[q] = pv0[l + 32 * q];
#pragma unroll
        for (int q = 0; q < 4; q++) p1[q] = pv1[l + 32 * q];

        float daa = 0.f, d0 = 0.f, n0 = 0.f, d1 = 0.f, n1 = 0.f;
#pragma unroll
        for (int q = 0; q < 4; q++) {
            daa += a4[q].x * a4[q].x + a4[q].y * a4[q].y + a4[q].z * a4[q].z + a4[q].w * a4[q].w;
            d0  += a4[q].x * p0[q].x + a4[q].y * p0[q].y + a4[q].z * p0[q].z + a4[q].w * p0[q].w;
            n0  += p0[q].x * p0[q].x + p0[q].y * p0[q].y + p0[q].z * p0[q].z + p0[q].w * p0[q].w;
            d1  += a4[q].x * p1[q].x + a4[q].y * p1[q].y + a4[q].z * p1[q].z + a4[q].w * p1[q].w;
            n1  += p1[q].x * p1[q].x + p1[q].y * p1[q].y + p1[q].z * p1[q].z + p1[q].w * p1[q].w;
        }
#pragma unroll
        for (int o = 16; o > 0; o >>= 1) {
            daa += __shfl_xor_sync(0xffffffffu, daa, o);
            d0  += __shfl_xor_sync(0xffffffffu, d0, o);
            n0  += __shfl_xor_sync(0xffffffffu, n0, o);
            d1  += __shfl_xor_sync(0xffffffffu, d1, o);
            n1  += __shfl_xor_sync(0xffffffffu, n1, o);
        }
        if (l == 0) {
            float ia = rsqrtf(daa);
            g_logits[2 * b]     = d0 * rsqrtf(n0) * ia * INV_T;
            g_logits[2 * b + 1] = d1 * rsqrtf(n1) * ia * INV_T;
        }
        return;
    }

    // ============ aa tiles: wait for normalize grid ============
    grid_dep_sync();

    __shared__ float rs_row[128][4];
    __shared__ float rs_col[128][2];

    const int idx = blockIdx.x;
    int bx = (int)((sqrtf(8.0f * idx + 1.0f) - 1.0f) * 0.5f);
    while ((bx + 1) * (bx + 2) / 2 <= idx) ++bx;
    while (bx * (bx + 1) / 2 > idx) --bx;
    const int by = idx - bx * (bx + 1) / 2;
    const bool diag = (bx == by);

    const int wr  = wid & 1;
    const int wc  = wid >> 1;
    const int row0 = by * 128;
    const int col0 = bx * 128;

    const uint32_t sa_base = smem_u32(dyn);
    const uint32_t sb_base = sa_base + 3 * TILE_BYTES;
    const char* gsrc = (const char*)g_abf16;

    const int ra = (l & 7) | (((l >> 3) & 1) << 3);
    const int sa_hi = l >> 4;
    const int rb = (l & 7) | ((l >> 4) << 3);
    const int sb_hi = (l >> 3) & 1;

    uint32_t offA[2], offB[2];
#pragma unroll
    for (int kc = 0; kc < 2; kc++) {
        offA[kc] = ra * 64 + (((2 * kc + sa_hi) ^ ((ra >> 1) & 3)) << 4);
        offB[kc] = rb * 64 + (((2 * kc + sb_hi) ^ ((rb >> 1) & 3)) << 4);
    }

    int ld_row[2], ld_slot[2];
    uint32_t ld_dst[2];
#pragma unroll
    for (int t = 0; t < 2; t++) {
        int i2 = tid + t * 256;
        ld_row[t]  = i2 >> 2;
        ld_slot[t] = i2 & 3;
        int sw = ld_slot[t] ^ ((ld_row[t] >> 1) & 3);
        ld_dst[t] = ld_row[t] * 64 + sw * 16;
    }

    float acc[4][4][4];
#pragma unroll
    for (int i = 0; i < 4; i++)
#pragma unroll
        for (int j = 0; j < 4; j++)
#pragma unroll
            for (int q = 0; q < 4; q++) acc[i][j][q] = 0.f;

#define ISSUE_CHUNK(c, nb) do {                                               \
    int kbyte = (c) * KC * 2;                                                 \
    _Pragma("unroll")                                                         \
    for (int t = 0; t < 2; t++) {                                             \
        const char* srcA = gsrc + ((size_t)(row0 + ld_row[t]) * ND) * 2 + kbyte + ld_slot[t] * 16; \
        const char* srcB = gsrc + ((size_t)(col0 + ld_row[t]) * ND) * 2 + kbyte + ld_slot[t] * 16; \
        asm volatile("cp.async.cg.shared.global [%0], [%1], 16;"              \
            :: "r"(sa_base + (nb) * TILE_BYTES + ld_dst[t]), "l"(srcA) : "memory"); \
        asm volatile("cp.async.cg.shared.global [%0], [%1], 16;"              \
            :: "r"(sb_base + (nb) * TILE_BYTES + ld_dst[t]), "l"(srcB) : "memory"); \
    }                                                                         \
    asm volatile("cp.async.commit_group;" ::: "memory");                      \
} while (0)

    ISSUE_CHUNK(0, 0);
    ISSUE_CHUNK(1, 1);

    for (int c = 0; c < NCHUNK; c++) {
        if (c < NCHUNK - 1) asm volatile("cp.async.wait_group 1;" ::: "memory");
        else                asm volatile("cp.async.wait_group 0;" ::: "memory");
        __syncthreads();

        int p = c + 2;
        if (p < NCHUNK) ISSUE_CHUNK(p, p % 3);

        const int buf = c % 3;
        const uint32_t aw = sa_base + buf * TILE_BYTES + wr * 64 * 64;
        const uint32_t bw = sb_base + buf * TILE_BYTES + wc * 32 * 64;

#pragma unroll
        for (int kc = 0; kc < 2; kc++) {
            uint32_t af[4][4];
#pragma unroll
            for (int mf = 0; mf < 4; mf++) {
                asm volatile("ldmatrix.sync.aligned.m8n8.x4.shared.b16 {%0,%1,%2,%3}, [%4];"
                    : "=r"(af[mf][0]), "=r"(af[mf][1]), "=r"(af[mf][2]), "=r"(af[mf][3])
                    : "r"(aw + mf * 16 * 64 + offA[kc]));
            }
            uint32_t bf[4][2];
#pragma unroll
            for (int p2 = 0; p2 < 2; p2++) {
                uint32_t r0, r1, r2, r3;
                asm volatile("ldmatrix.sync.aligned.m8n8.x4.shared.b16 {%0,%1,%2,%3}, [%4];"
                    : "=r"(r0), "=r"(r1), "=r"(r2), "=r"(r3)
                    : "r"(bw + p2 * 16 * 64 + offB[kc]));
                bf[2 * p2][0] = r0; bf[2 * p2][1] = r1;
                bf[2 * p2 + 1][0] = r2; bf[2 * p2 + 1][1] = r3;
            }
#pragma unroll
            for (int mf = 0; mf < 4; mf++)
#pragma unroll
                for (int nf = 0; nf < 4; nf++) {
                    asm volatile(
                        "mma.sync.aligned.m16n8k16.row.col.f32.bf16.bf16.f32 "
                        "{%0,%1,%2,%3}, {%4,%5,%6,%7}, {%8,%9}, {%0,%1,%2,%3};"
                        : "+f"(acc[mf][nf][0]), "+f"(acc[mf][nf][1]),
                          "+f"(acc[mf][nf][2]), "+f"(acc[mf][nf][3])
                        : "r"(af[mf][0]), "r"(af[mf][1]), "r"(af[mf][2]), "r"(af[mf][3]),
                          "r"(bf[nf][0]), "r"(bf[nf][1]));
                }
        }
    }
    __syncthreads();

    const int qrow = l >> 2;
    const int qcol = 2 * (l & 3);

    float cs0[4], cs1[4];
#pragma unroll
    for (int nf = 0; nf < 4; nf++) { cs0[nf] = 0.f; cs1[nf] = 0.f; }

#pragma unroll
    for (int mf = 0; mf < 4; mf++) {
        float slo = 0.f, shi = 0.f;
        int rlo = wr * 64 + mf * 16 + qrow;
#pragma unroll
        for (int nf = 0; nf < 4; nf++) {
            int cb = wc * 32 + nf * 8 + qcol;
            float e0 = ex2(acc[mf][nf][0] * EXP2_SCALE);
            float e1 = ex2(acc[mf][nf][1] * EXP2_SCALE);
            float e2 = ex2(acc[mf][nf][2] * EXP2_SCALE);
            float e3 = ex2(acc[mf][nf][3] * EXP2_SCALE);
            if (diag) {
                if (rlo == cb)         e0 = 0.f;
                if (rlo == cb + 1)     e1 = 0.f;
                if (rlo + 8 == cb)     e2 = 0.f;
                if (rlo + 8 == cb + 1) e3 = 0.f;
            }
            slo += e0 + e1;
            shi += e2 + e3;
            cs0[nf] += e0 + e2;
            cs1[nf] += e1 + e3;
        }
        slo += __shfl_xor_sync(0xffffffffu, slo, 1);
        slo += __shfl_xor_sync(0xffffffffu, slo, 2);
        shi += __shfl_xor_sync(0xffffffffu, shi, 1);
        shi += __shfl_xor_sync(0xffffffffu, shi, 2);
        if ((l & 3) == 0) {
            rs_row[rlo][wc]     = slo;
            rs_row[rlo + 8][wc] = shi;
        }
    }

    if (!diag) {
#pragma unroll
        for (int nf = 0; nf < 4; nf++) {
#pragma unroll
            for (int o = 4; o <= 16; o <<= 1) {
                cs0[nf] += __shfl_xor_sync(0xffffffffu, cs0[nf], o);
                cs1[nf] += __shfl_xor_sync(0xffffffffu, cs1[nf], o);
            }
            if (l < 4) {
                int cb = wc * 32 + nf * 8 + qcol;
                rs_col[cb][wr]     = cs0[nf];
                rs_col[cb + 1][wr] = cs1[nf];
            }
        }
    }
    __syncthreads();

    if (tid < 128) {
        float s = rs_row[tid][0] + rs_row[tid][1] + rs_row[tid][2] + rs_row[tid][3];
        g_partial[(size_t)(row0 + tid) * NCOLT + bx] = s;
        if (!diag) {
            float csum = rs_col[tid][0] + rs_col[tid][1];
            g_partial[(size_t)(col0 + tid) * NCOLT + by] = csum;
        }
    }
}

// ---------------------------------------------------------------------------
// 3) loss finish: grid-dep-sync on aa kernel; np from g_partial, logits ready.
// ---------------------------------------------------------------------------
__global__ __launch_bounds__(256) void loss_kernel(float* __restrict__ out) {
    grid_dep_sync();

    __shared__ float sh[8];
    __shared__ int slast;
    int warp = threadIdx.x >> 5;
    int lane = threadIdx.x & 31;
    int b    = blockIdx.x * 8 + warp;

    float np = g_partial[(size_t)b * NCOLT + lane];
#pragma unroll
    for (int o = 16; o > 0; o >>= 1) np += __shfl_xor_sync(0xffffffffu, np, o);

    if (lane == 0) {
        float ps0 = g_logits[2 * b];
        float ps1 = g_logits[2 * b + 1];
        float l0  = logf(expf(ps0) + np + 1e-8f) - ps0;
        float l1  = logf(expf(ps1) + np + 1e-8f) - ps1;
        sh[warp] = l0 + l1;
    }
    __syncthreads();

    if (threadIdx.x == 0) {
        float s = 0.f;
#pragma unroll
        for (int w = 0; w < 8; w++) s += sh[w];
        g_losspart[blockIdx.x] = s;
        __threadfence();
        int old = atomicAdd(&g_count, 1);
        slast = (old == NLOSSB - 1) ? 1 : 0;
    }
    __syncthreads();

    if (slast) {
        __shared__ float fr[256];
        float s = g_losspart[threadIdx.x] + g_losspart[threadIdx.x + 256];
        fr[threadIdx.x] = s;
        __syncthreads();
        for (int o = 128; o > 0; o >>= 1) {
            if (threadIdx.x < o) fr[threadIdx.x] += fr[threadIdx.x + o];
            __syncthreads();
        }
        if (threadIdx.x == 0) out[0] = fr[0] * (1.0f / (float)NPOS);
    }
}

// ---------------------------------------------------------------------------
extern "C" void kernel_launch(void* const* d_in, const int* in_sizes, int n_in,
                              void* d_out, int out_size) {
    const float* anchor = (const float*)d_in[0];
    const float* pos    = (const float*)d_in[1];
    if (n_in >= 2 && in_sizes[0] > in_sizes[1]) {
        const float* t = anchor; anchor = pos; pos = t;
    }

    cudaFuncSetAttribute(aa_mma_kernel, cudaFuncAttributeMaxDynamicSharedMemorySize,
                         SMEM_AA);

    normalize_kernel<<<NB / 4, 128>>>(anchor);

    // PDL: pre-launch aa kernel while normalize drains
    {
        cudaLaunchAttribute attrs[1];
        attrs[0].id = cudaLaunchAttributeProgrammaticStreamSerialization;
        attrs[0].val.programmaticStreamSerializationAllowed = 1;
        cudaLaunchConfig_t cfg = {};
        cfg.gridDim = dim3(NTILE + POSB);
        cfg.blockDim = dim3(256);
        cfg.dynamicSmemBytes = SMEM_AA;
        cfg.attrs = attrs;
        cfg.numAttrs = 1;
        cudaLaunchKernelEx(&cfg, aa_mma_kernel, anchor, pos);
    }

    // PDL: pre-launch loss kernel while aa kernel drains
    {
        cudaLaunchAttribute attrs[1];
        attrs[0].id = cudaLaunchAttributeProgrammaticStreamSerialization;
        attrs[0].val.programmaticStreamSerializationAllowed = 1;
        cudaLaunchConfig_t cfg = {};
        cfg.gridDim = dim3(NLOSSB);
        cfg.blockDim = dim3(256);
        cfg.dynamicSmemBytes = 0;
        cfg.attrs = attrs;
        cfg.numAttrs = 1;
        cudaLaunchKernelEx(&cfg, loss_kernel, (float*)d_out);
    }
}